// round 5
// baseline (speedup 1.0000x reference)
#include <cuda_runtime.h>
#include <cuda_bf16.h>

// SoftTimeAttention: out[b,i,:] = sum_j w_ij * h[b,j,:],
//   w_ij = softmax_j( -(T*(t_i - t_j))^2 ), T=4096, tau=1.
// Gaussian width in t-space is 1/T; with t ~ U[0,1] only ~13 keys per query
// have non-underflowing fp32 weight. Self key (j==i) has logit exactly 0 ==
// max, so weights are exp(-(T*dt)^2) with no max-shift; sum >= 1 always.
// Keys with (T*dt)^2 > 40 contribute < 4096*e^-40 ~ 2e-14 relative mass.
//
// Kernel 1: per-batch counting sort of t into NB=4096 buckets (bucket width
//           1/NB = 2.44e-4 < cutoff radius 1.54e-3). float4 input loads.
// Kernel 2: one warp per FOUR consecutive sorted queries. Their key windows
//           overlap almost entirely, so each 1KB h row is loaded once and
//           FMA'd into 4 accumulator sets (~3x gather-traffic reduction).

#define TT 4096            // sequence length (== softmax scale T)
#define HH 256             // head dim
#define NB 4096            // buckets
#define RADIUS 7           // ceil(sqrt(40)/TT * NB) = ceil(6.3246) = 7
#define CUTF 40.0f
#define MAXB 8
#define QPW 4              // sorted queries per warp

__device__ float g_ct  [MAXB * TT];         // t values reordered by bucket
__device__ int   g_cidx[MAXB * TT];         // original indices reordered
__device__ int   g_bstart[MAXB * (NB + 1)]; // bucket start offsets (+ total)

__device__ __forceinline__ int bucket_of(float v) {
    int bi = (int)(v * (float)NB);
    bi = bi < 0 ? 0 : bi;
    bi = bi > NB - 1 ? NB - 1 : bi;
    return bi;
}

// ---------------------------------------------------------------------------
// Kernel 1: counting sort by bucket. One 1024-thread CTA per batch.
// ---------------------------------------------------------------------------
__global__ void __launch_bounds__(1024, 1)
bucket_kernel(const float* __restrict__ t) {
    __shared__ int hist[NB];   // counts -> exclusive starts
    __shared__ int cur[NB];    // scatter cursors
    __shared__ int wsum[32];

    const int b   = blockIdx.x;
    const int tid = threadIdx.x;             // 1024 threads
    const float4* tb4 = (const float4*)(t + (size_t)b * TT);

    for (int i = tid; i < NB; i += 1024) hist[i] = 0;
    __syncthreads();

    // One float4 per thread covers TT = 4096 exactly.
    const float4 tv = __ldg(tb4 + tid);
    atomicAdd(&hist[bucket_of(tv.x)], 1);
    atomicAdd(&hist[bucket_of(tv.y)], 1);
    atomicAdd(&hist[bucket_of(tv.z)], 1);
    atomicAdd(&hist[bucket_of(tv.w)], 1);
    __syncthreads();

    // Hierarchical exclusive scan over 4096 counts (4 per thread).
    const int base = tid * 4;
    int s0 = hist[base], s1 = hist[base + 1], s2 = hist[base + 2], s3 = hist[base + 3];
    int tot = s0 + s1 + s2 + s3;

    const int lane = tid & 31;
    const int wid  = tid >> 5;
    int v = tot;
    #pragma unroll
    for (int o = 1; o < 32; o <<= 1) {
        int u = __shfl_up_sync(0xFFFFFFFFu, v, o);
        if (lane >= o) v += u;
    }
    if (lane == 31) wsum[wid] = v;
    __syncthreads();
    if (wid == 0) {
        int w = wsum[lane];
        #pragma unroll
        for (int o = 1; o < 32; o <<= 1) {
            int u = __shfl_up_sync(0xFFFFFFFFu, w, o);
            if (lane >= o) w += u;
        }
        wsum[lane] = w;   // inclusive scan of per-warp totals
    }
    __syncthreads();

    int excl = v - tot + (wid > 0 ? wsum[wid - 1] : 0);
    const int st0 = excl, st1 = st0 + s0, st2 = st1 + s1, st3 = st2 + s2;

    cur[base] = st0; cur[base + 1] = st1; cur[base + 2] = st2; cur[base + 3] = st3;

    int* gb = g_bstart + b * (NB + 1);
    gb[base] = st0; gb[base + 1] = st1; gb[base + 2] = st2; gb[base + 3] = st3;
    if (tid == 0) gb[NB] = TT;
    __syncthreads();

    // Scatter t and original index by bucket (reuse the registered float4).
    float* ct = g_ct   + b * TT;
    int*   ci = g_cidx + b * TT;
    {
        const int i0 = tid * 4;
        int p;
        p = atomicAdd(&cur[bucket_of(tv.x)], 1); ct[p] = tv.x; ci[p] = i0 + 0;
        p = atomicAdd(&cur[bucket_of(tv.y)], 1); ct[p] = tv.y; ci[p] = i0 + 1;
        p = atomicAdd(&cur[bucket_of(tv.z)], 1); ct[p] = tv.z; ci[p] = i0 + 2;
        p = atomicAdd(&cur[bucket_of(tv.w)], 1); ct[p] = tv.w; ci[p] = i0 + 3;
    }
}

// ---------------------------------------------------------------------------
// Kernel 2: one warp per QPW consecutive sorted queries. 8 warps / CTA.
// ---------------------------------------------------------------------------
__global__ void __launch_bounds__(256)
attn_kernel(const float* __restrict__ h, float* __restrict__ out) {
    const int gw   = (blockIdx.x * 256 + threadIdx.x) >> 5; // global warp id
    const int lane = threadIdx.x & 31;
    const int b  = gw >> 10;                 // / (TT/QPW = 1024)
    const int p0 = (gw & 1023) * QPW;        // first sorted position

    const float* ct = g_ct   + ((size_t)b << 12);
    const int*   ci = g_cidx + ((size_t)b << 12);

    float tq[QPW];
    int   iq[QPW];
    #pragma unroll
    for (int q = 0; q < QPW; ++q) {
        tq[q] = __ldg(ct + p0 + q);     // sorted: tq[0] <= ... <= tq[3]
        iq[q] = __ldg(ci + p0 + q);
    }

    // Union key window across the QPW queries.
    const int* gb = g_bstart + b * (NB + 1);
    const int lob = bucket_of(tq[0]) - RADIUS;
    const int hib = bucket_of(tq[QPW - 1]) + RADIUS + 1;
    const int lo = __ldg(gb + (lob < 0 ? 0 : lob));
    const int hi = __ldg(gb + (hib > NB ? NB : hib));

    const float* hb = h + (((size_t)b << 12)) * HH;

    float4 a0[QPW], a1[QPW];
    float  sumw[QPW];
    #pragma unroll
    for (int q = 0; q < QPW; ++q) {
        a0[q] = make_float4(0.f, 0.f, 0.f, 0.f);
        a1[q] = make_float4(0.f, 0.f, 0.f, 0.f);
        sumw[q] = 0.f;
    }

    for (int j = lo; j < hi; ++j) {
        const float tk = __ldg(ct + j);
        // One row load serves all QPW queries.
        const float4* row = (const float4*)(hb + (size_t)__ldg(ci + j) * HH);
        const float4 v0 = __ldg(row + lane);       // cols [lane*4, +4)
        const float4 v1 = __ldg(row + 32 + lane);  // cols [128+lane*4, +4)

        #pragma unroll
        for (int q = 0; q < QPW; ++q) {
            const float d  = (float)TT * (tq[q] - tk);
            float d2 = d * d;
            // Out-of-cutoff -> force EX2 input far below denormal range so the
            // weight is unconditionally +0.0f.
            d2 = d2 > CUTF ? 999.0f : d2;
            const float w = __expf(-d2);
            sumw[q] += w;
            a0[q].x = fmaf(w, v0.x, a0[q].x); a0[q].y = fmaf(w, v0.y, a0[q].y);
            a0[q].z = fmaf(w, v0.z, a0[q].z); a0[q].w = fmaf(w, v0.w, a0[q].w);
            a1[q].x = fmaf(w, v1.x, a1[q].x); a1[q].y = fmaf(w, v1.y, a1[q].y);
            a1[q].z = fmaf(w, v1.z, a1[q].z); a1[q].w = fmaf(w, v1.w, a1[q].w);
        }
    }

    #pragma unroll
    for (int q = 0; q < QPW; ++q) {
        const float inv = 1.0f / sumw[q];  // sumw >= 1 (self key weight == 1)
        float4 o0 = make_float4(a0[q].x * inv, a0[q].y * inv,
                                a0[q].z * inv, a0[q].w * inv);
        float4 o1 = make_float4(a1[q].x * inv, a1[q].y * inv,
                                a1[q].z * inv, a1[q].w * inv);
        float4* orow = (float4*)(out + ((size_t)(((size_t)b << 12) + iq[q])) * HH);
        orow[lane]      = o0;
        orow[32 + lane] = o1;
    }
}

// ---------------------------------------------------------------------------
extern "C" void kernel_launch(void* const* d_in, const int* in_sizes, int n_in,
                              void* d_out, int out_size) {
    const float* h = (const float*)d_in[0];   // h_seq: (B, T, H) fp32
    const float* t = (const float*)d_in[1];   // t:     (B, T, 1) fp32
    float* out = (float*)d_out;               // (B, T, H) fp32

    int B = in_sizes[1] / TT;
    if (B < 1) B = 1;
    if (B > MAXB) B = MAXB;

    bucket_kernel<<<B, 1024>>>(t);
    // B * (TT/QPW) warps, 8 warps per CTA.
    attn_kernel<<<B * (TT / QPW / 8), 256>>>(h, out);
}